// round 2
// baseline (speedup 1.0000x reference)
#include <cuda_runtime.h>
#include <cuda_bf16.h>

#define NQ    18
#define NBAT  16

// Transfer weight W_i(s | sp) for the 8-state bond s = (w<<2)|(y<<1)|y'.
//   d  = w ^ w_prev         (layer-1 physical bit after undoing 2nd CNOT chain)
//   R_i[d][y]: RY(phi_i) matrix  [[c1,-s1],[s1,c1]]  -> R[0][0]=c1, R[0][1]=-s1, R[1][0]=s1, R[1][1]=c1
//   a_i[y ^ y_prev]: layer-0 amplitude on |0>  -> a[0]=c0, a[1]=s0
__device__ __forceinline__ float xfer_w(int s, int sp,
                                        float c0, float s0,
                                        float c1, float s1) {
    const int w   =  s >> 2,        y   = (s >> 1) & 1,  yq  =  s & 1;
    const int wp  = sp >> 2,        ysp = (sp >> 1) & 1, yqp = sp & 1;
    const int d   = w ^ wp;
    const float r1 = d ? (y  ? c1 : s1) : (y  ? -s1 : c1);
    const float r2 = d ? (yq ? c1 : s1) : (yq ? -s1 : c1);
    const float a1 = (y  ^ ysp) ? s0 : c0;
    const float a2 = (yq ^ yqp) ? s0 : c0;
    return r1 * r2 * a1 * a2;
}

__global__ void __launch_bounds__(32, 1)
quantum_mps_kernel(const float* __restrict__ in, float* __restrict__ out) {
    const int b = threadIdx.x;
    if (b >= NBAT) return;

    const float* ang = in + b * (2 * NQ);   // [layer, qubit]

    float c0[NQ], s0[NQ], c1[NQ], s1[NQ];
    #pragma unroll
    for (int i = 0; i < NQ; i++) {
        float h0 = 0.5f * ang[i];        // layer 0 half-angle
        float h1 = 0.5f * ang[NQ + i];   // layer 1 half-angle
        sincosf(h0, &s0[i], &c0[i]);
        sincosf(h1, &s1[i], &c1[i]);
    }

    // ---- backward sweep: suffix vectors suf[k](sp) = sum_{s} W_{k+1}(s|sp) * suf[k+1](s)
    float suf[NQ][8];
    #pragma unroll
    for (int s = 0; s < 8; s++) suf[NQ - 1][s] = 1.0f;

    for (int k = NQ - 2; k >= 0; k--) {
        const float kc0 = c0[k + 1], ks0 = s0[k + 1];
        const float kc1 = c1[k + 1], ks1 = s1[k + 1];
        #pragma unroll
        for (int sp = 0; sp < 8; sp++) {
            float acc = 0.0f;
            #pragma unroll
            for (int s = 0; s < 8; s++)
                acc = fmaf(xfer_w(s, sp, kc0, ks0, kc1, ks1), suf[k + 1][s], acc);
            suf[k][sp] = acc;
        }
    }

    // ---- forward sweep with fused readout:
    // L_i = L_{i-1} T_i ;  <Z_i> = sum_s (-1)^{w(s)} L_i(s) * suf[i](s)
    float prev[8];
    #pragma unroll
    for (int s = 0; s < 8; s++) prev[s] = 0.0f;
    prev[0] = 1.0f;   // s_{-1} = (w=0, y=0, y'=0)

    for (int i = 0; i < NQ; i++) {
        const float ic0 = c0[i], is0 = s0[i];
        const float ic1 = c1[i], is1 = s1[i];
        float cur[8];
        #pragma unroll
        for (int s = 0; s < 8; s++) {
            float acc = 0.0f;
            #pragma unroll
            for (int sp = 0; sp < 8; sp++)
                acc = fmaf(xfer_w(s, sp, ic0, is0, ic1, is1), prev[sp], acc);
            cur[s] = acc;
        }
        float z = 0.0f;
        #pragma unroll
        for (int s = 0; s < 8; s++) {
            float term = cur[s] * suf[i][s];
            z += (s & 4) ? -term : term;
        }
        out[b * NQ + i] = z;
        #pragma unroll
        for (int s = 0; s < 8; s++) prev[s] = cur[s];
    }
}

extern "C" void kernel_launch(void* const* d_in, const int* in_sizes, int n_in,
                              void* d_out, int out_size) {
    const float* in  = (const float*)d_in[0];
    float*       out = (float*)d_out;
    quantum_mps_kernel<<<1, 32>>>(in, out);
}

// round 3
// speedup vs baseline: 1.8848x; 1.8848x over previous
#include <cuda_runtime.h>
#include <cuda_bf16.h>

#define NQ    18
#define NBAT  16

// Transfer operator for the 8-state bond s = (w<<2)|(y<<1)|y' factorizes into
// three 2x2 butterflies (tensor-product structure):
//   bit1 (y) : a1 -> c0*own + s0*flip(bit1)
//   bit0 (y'): a2 -> c0*own + s0*flip(bit0)
//   bit2 (w) : rho_d(y,y') = r1(d,y)*r1(d,y'),  r1(0,·)={c1,-s1}, r1(1,·)={s1,c1}
// Forward order: A(bit1), B(bit0), C(bit2).  Transposed (backward): C, A, B.

__global__ void __launch_bounds__(32, 1)
quantum_mps_kernel(const float* __restrict__ in, float* __restrict__ out) {
    const int b = threadIdx.x;
    if (b >= NBAT) return;

    const float* ang = in + b * (2 * NQ);   // [layer, qubit]

    float c0[NQ], s0[NQ], c1[NQ], s1[NQ];
    #pragma unroll
    for (int i = 0; i < NQ; i++) {
        __sincosf(0.5f * ang[i],      &s0[i], &c0[i]);   // layer 0
        __sincosf(0.5f * ang[NQ + i], &s1[i], &c1[i]);   // layer 1
    }

    // ---- backward sweep: suf[k] = T_{k+1}^T suf[k+1]
    float suf[NQ][8];
    #pragma unroll
    for (int s = 0; s < 8; s++) suf[NQ - 1][s] = 1.0f;

    #pragma unroll
    for (int k = NQ - 2; k >= 0; k--) {
        const float C0 = c0[k + 1], S0 = s0[k + 1];
        const float C1 = c1[k + 1], S1 = s1[k + 1];
        const float cc = C1 * C1, ss = S1 * S1, cs = C1 * S1;

        float t[8], v[8];
        // step C (bit2, w): coefficients depend on (y,y') = s&3
        #pragma unroll
        for (int s = 0; s < 8; s++) {
            const int yy = s & 3;
            const float r0 = (yy == 0) ? cc : (yy == 3) ? ss : -cs;
            const float r1 = (yy == 0) ? ss : (yy == 3) ? cc :  cs;
            t[s] = fmaf(r0, suf[k + 1][s], r1 * suf[k + 1][s ^ 4]);
        }
        // step A^T (bit1)
        #pragma unroll
        for (int s = 0; s < 8; s++) v[s] = fmaf(C0, t[s], S0 * t[s ^ 2]);
        // step B^T (bit0)
        #pragma unroll
        for (int s = 0; s < 8; s++) suf[k][s] = fmaf(C0, v[s], S0 * v[s ^ 1]);
    }

    // ---- forward sweep with fused readout
    float prev[8];
    #pragma unroll
    for (int s = 0; s < 8; s++) prev[s] = 0.0f;
    prev[0] = 1.0f;   // bond state (w=0,y=0,y'=0)

    #pragma unroll
    for (int i = 0; i < NQ; i++) {
        const float C0 = c0[i], S0 = s0[i];
        const float C1 = c1[i], S1 = s1[i];
        const float cc = C1 * C1, ss = S1 * S1, cs = C1 * S1;

        float t[8], v[8];
        // step A (bit1)
        #pragma unroll
        for (int s = 0; s < 8; s++) t[s] = fmaf(C0, prev[s], S0 * prev[s ^ 2]);
        // step B (bit0)
        #pragma unroll
        for (int s = 0; s < 8; s++) v[s] = fmaf(C0, t[s], S0 * t[s ^ 1]);
        // step C (bit2)
        #pragma unroll
        for (int s = 0; s < 8; s++) {
            const int yy = s & 3;
            const float r0 = (yy == 0) ? cc : (yy == 3) ? ss : -cs;
            const float r1 = (yy == 0) ? ss : (yy == 3) ? cc :  cs;
            prev[s] = fmaf(r0, v[s], r1 * v[s ^ 4]);
        }

        // readout: <Z_i> = sum_s (-1)^w L_i[s] * suf_i[s]
        float z = 0.0f;
        #pragma unroll
        for (int s = 0; s < 8; s++) {
            const float term = prev[s] * suf[i][s];
            z += (s & 4) ? -term : term;
        }
        out[b * NQ + i] = z;
    }
}

extern "C" void kernel_launch(void* const* d_in, const int* in_sizes, int n_in,
                              void* d_out, int out_size) {
    const float* in  = (const float*)d_in[0];
    float*       out = (float*)d_out;
    quantum_mps_kernel<<<1, 32>>>(in, out);
}

// round 4
// speedup vs baseline: 1.9384x; 1.0284x over previous
#include <cuda_runtime.h>
#include <cuda_bf16.h>

#define NQ    18
#define NBAT  16

// Bond state s = (w<<2)|(y<<1)|y'. Transfer operator factorizes into three
// symmetric 2x2 butterflies; transpose sweep = same formulas, reversed order.
// Warp 0: forward sweep (stores L_i to shared). Warp 1: backward sweep
// (stores suf_k to shared). Then both warps split the 18 readouts.

__global__ void __launch_bounds__(64, 1)
quantum_mps_kernel(const float* __restrict__ in, float* __restrict__ out) {
    __shared__ float sL[NQ][NBAT][8];   // forward prefix vectors
    __shared__ float sS[NQ][NBAT][8];   // backward suffix vectors

    const int tid = threadIdx.x;
    const int wid = tid >> 5;
    const int b   = tid & 31;           // batch index within warp
    const bool active = (b < NBAT);

    if (active) {
        const float* ang = in + b * (2 * NQ);
        float c0[NQ], s0[NQ], c1[NQ], s1[NQ];
        #pragma unroll
        for (int i = 0; i < NQ; i++) {
            __sincosf(0.5f * ang[i],      &s0[i], &c0[i]);   // layer 0
            __sincosf(0.5f * ang[NQ + i], &s1[i], &c1[i]);   // layer 1
        }

        if (wid == 0) {
            // ---- forward sweep: L_i = T_i L_{i-1}
            float p[8] = {1.f, 0.f, 0.f, 0.f, 0.f, 0.f, 0.f, 0.f};
            #pragma unroll
            for (int i = 0; i < NQ; i++) {
                const float C0 = c0[i], S0 = s0[i];
                const float cc = c1[i] * c1[i], ss = s1[i] * s1[i], cs = c1[i] * s1[i];
                float t[8], v[8];
                #pragma unroll
                for (int s = 0; s < 8; s++) t[s] = fmaf(C0, p[s], S0 * p[s ^ 2]);
                #pragma unroll
                for (int s = 0; s < 8; s++) v[s] = fmaf(C0, t[s], S0 * t[s ^ 1]);
                #pragma unroll
                for (int s = 0; s < 8; s++) {
                    const int yy = s & 3;
                    const float r0 = (yy == 0) ? cc : (yy == 3) ? ss : -cs;
                    const float r1 = (yy == 0) ? ss : (yy == 3) ? cc :  cs;
                    p[s] = fmaf(r0, v[s], r1 * v[s ^ 4]);
                }
                #pragma unroll
                for (int s = 0; s < 8; s++) sL[i][b][s] = p[s];
            }
        } else {
            // ---- backward sweep: suf_k = T_{k+1}^T suf_{k+1}
            float u[8];
            #pragma unroll
            for (int s = 0; s < 8; s++) { u[s] = 1.f; sS[NQ - 1][b][s] = 1.f; }
            #pragma unroll
            for (int k = NQ - 2; k >= 0; k--) {
                const float C0 = c0[k + 1], S0 = s0[k + 1];
                const float cc = c1[k + 1] * c1[k + 1];
                const float ss = s1[k + 1] * s1[k + 1];
                const float cs = c1[k + 1] * s1[k + 1];
                float t[8], v[8];
                #pragma unroll
                for (int s = 0; s < 8; s++) {
                    const int yy = s & 3;
                    const float r0 = (yy == 0) ? cc : (yy == 3) ? ss : -cs;
                    const float r1 = (yy == 0) ? ss : (yy == 3) ? cc :  cs;
                    t[s] = fmaf(r0, u[s], r1 * u[s ^ 4]);
                }
                #pragma unroll
                for (int s = 0; s < 8; s++) v[s] = fmaf(C0, t[s], S0 * t[s ^ 2]);
                #pragma unroll
                for (int s = 0; s < 8; s++) {
                    u[s] = fmaf(C0, v[s], S0 * v[s ^ 1]);
                    sS[k][b][s] = u[s];
                }
            }
        }
    }

    __syncthreads();

    // ---- readout, split 9 sites per warp: Z_i = sum_s (-1)^w L_i[s] suf_i[s]
    if (active) {
        const int i0 = wid * 9;
        #pragma unroll
        for (int j = 0; j < 9; j++) {
            const int i = i0 + j;
            float m[8];
            #pragma unroll
            for (int s = 0; s < 8; s++) m[s] = sL[i][b][s] * sS[i][b][s];
            const float z = ((m[0] + m[1]) + (m[2] + m[3]))
                          - ((m[4] + m[5]) + (m[6] + m[7]));
            out[b * NQ + i] = z;
        }
    }
}

extern "C" void kernel_launch(void* const* d_in, const int* in_sizes, int n_in,
                              void* d_out, int out_size) {
    const float* in  = (const float*)d_in[0];
    float*       out = (float*)d_out;
    quantum_mps_kernel<<<1, 64>>>(in, out);
}

// round 5
// speedup vs baseline: 1.9663x; 1.0144x over previous
#include <cuda_runtime.h>
#include <cuda_bf16.h>

#define NQ    18
#define NBAT  16

typedef unsigned long long u64;

// ---- f32x2 packed helpers (sm_103a FFMA2 path; only reachable via PTX) ----
__device__ __forceinline__ u64 pk(float lo, float hi) {
    u64 r; asm("mov.b64 %0,{%1,%2};" : "=l"(r) : "f"(lo), "f"(hi)); return r;
}
__device__ __forceinline__ void upk(u64 v, float& lo, float& hi) {
    asm("mov.b64 {%0,%1},%2;" : "=f"(lo), "=f"(hi) : "l"(v));
}
__device__ __forceinline__ u64 fma2(u64 a, u64 b, u64 c) {
    u64 d; asm("fma.rn.f32x2 %0,%1,%2,%3;" : "=l"(d) : "l"(a), "l"(b), "l"(c)); return d;
}
__device__ __forceinline__ u64 mul2(u64 a, u64 b) {
    u64 d; asm("mul.rn.f32x2 %0,%1,%2;" : "=l"(d) : "l"(a), "l"(b)); return d;
}
__device__ __forceinline__ u64 add2(u64 a, u64 b) {
    u64 d; asm("add.rn.f32x2 %0,%1,%2;" : "=l"(d) : "l"(a), "l"(b)); return d;
}

// Bond state s = (w<<2)|(y<<1)|y'; packed as pairs P[j] = (state 2j, state 2j+1).
// Site operator = A(bit1) * B(bit0) * C(bit2):
//   A: t[s] = C0*p[s] + S0*p[s^2]        -> pair partner j^1 (packed)
//   B: v[s] = C0*t[s] + S0*t[s^1]        -> intra-pair (scalar)
//   C: p'[s]= r0(yy)*v[s] + r1(yy)*v[s^4]-> pair partner j^2 (packed)
//     r0: yy0->cc yy3->ss else -cs ; r1: yy0->ss yy3->cc else cs
//   packed coeffs: even j: r0=(cc,-cs) r1=(ss,cs); odd j: r0=(-cs,ss) r1=(cs,cc)
// All three stages are symmetric => transpose sweep uses identical formulas
// in reverse order (C, A, B).

// stride 5 u64 per lane (40B = 10 words): 10*b mod 32 distinct for b<16 -> conflict-free
__shared__ u64 g_cst[NQ][NBAT][5];
__shared__ u64 g_sL [NQ][NBAT][5];   // forward prefix vectors (4 used + pad)
__shared__ u64 g_sS [NQ][NBAT][5];   // backward suffix vectors

__global__ void __launch_bounds__(128, 1)
quantum_mps_kernel(const float* __restrict__ in, float* __restrict__ out) {
    const int tid = threadIdx.x;
    const int wid = tid >> 5;
    const int b   = tid & 31;
    const bool active = (b < NBAT);

    // ---- phase 1: warps 2,3 produce per-site packed coefficient tables ----
    if (active && wid >= 2) {
        const int i0 = (wid == 2) ? 0 : 9;
        const float* ang = in + b * (2 * NQ);
        #pragma unroll
        for (int j = 0; j < 9; j++) {
            const int i = i0 + j;
            float c0, s0, c1, s1;
            __sincosf(0.5f * ang[i],      &s0, &c0);
            __sincosf(0.5f * ang[NQ + i], &s1, &c1);
            const float cc = c1 * c1, ss = s1 * s1, cs = c1 * s1, ncs = -cs;
            g_cst[i][b][0] = pk(c0,  s0);
            g_cst[i][b][1] = pk(cc,  ncs);   // r0, even pairs
            g_cst[i][b][2] = pk(ncs, ss);    // r0, odd pairs
            g_cst[i][b][3] = pk(ss,  cs);    // r1, even pairs
            g_cst[i][b][4] = pk(cs,  cc);    // r1, odd pairs
        }
    }
    __syncthreads();

    // ---- phase 2: warp 0 forward sweep, warp 1 backward sweep ----
    if (active && wid == 0) {
        u64 P0 = pk(1.f, 0.f), P1 = pk(0.f, 0.f), P2 = P1, P3 = P1;
        #pragma unroll
        for (int i = 0; i < NQ; i++) {
            const u64 k0  = g_cst[i][b][0];
            const u64 r0e = g_cst[i][b][1], r0o = g_cst[i][b][2];
            const u64 r1e = g_cst[i][b][3], r1o = g_cst[i][b][4];
            float C0, S0; upk(k0, C0, S0);
            const u64 C0p = pk(C0, C0), S0p = pk(S0, S0);
            // A (packed, partner j^1)
            const u64 T0 = fma2(C0p, P0, mul2(S0p, P1));
            const u64 T1 = fma2(C0p, P1, mul2(S0p, P0));
            const u64 T2 = fma2(C0p, P2, mul2(S0p, P3));
            const u64 T3 = fma2(C0p, P3, mul2(S0p, P2));
            // B (scalar, intra-pair)
            float t0,t1,t2,t3,t4,t5,t6,t7;
            upk(T0,t0,t1); upk(T1,t2,t3); upk(T2,t4,t5); upk(T3,t6,t7);
            const u64 V0 = pk(fmaf(C0,t0,S0*t1), fmaf(C0,t1,S0*t0));
            const u64 V1 = pk(fmaf(C0,t2,S0*t3), fmaf(C0,t3,S0*t2));
            const u64 V2 = pk(fmaf(C0,t4,S0*t5), fmaf(C0,t5,S0*t4));
            const u64 V3 = pk(fmaf(C0,t6,S0*t7), fmaf(C0,t7,S0*t6));
            // C (packed, partner j^2)
            P0 = fma2(r0e, V0, mul2(r1e, V2));
            P1 = fma2(r0o, V1, mul2(r1o, V3));
            P2 = fma2(r0e, V2, mul2(r1e, V0));
            P3 = fma2(r0o, V3, mul2(r1o, V1));
            g_sL[i][b][0] = P0; g_sL[i][b][1] = P1;
            g_sL[i][b][2] = P2; g_sL[i][b][3] = P3;
        }
    } else if (active && wid == 1) {
        u64 U0 = pk(1.f, 1.f), U1 = U0, U2 = U0, U3 = U0;
        g_sS[NQ-1][b][0] = U0; g_sS[NQ-1][b][1] = U1;
        g_sS[NQ-1][b][2] = U2; g_sS[NQ-1][b][3] = U3;
        #pragma unroll
        for (int k = NQ - 2; k >= 0; k--) {
            const int i = k + 1;
            const u64 k0  = g_cst[i][b][0];
            const u64 r0e = g_cst[i][b][1], r0o = g_cst[i][b][2];
            const u64 r1e = g_cst[i][b][3], r1o = g_cst[i][b][4];
            float C0, S0; upk(k0, C0, S0);
            const u64 C0p = pk(C0, C0), S0p = pk(S0, S0);
            // C^T = C (packed)
            const u64 T0 = fma2(r0e, U0, mul2(r1e, U2));
            const u64 T1 = fma2(r0o, U1, mul2(r1o, U3));
            const u64 T2 = fma2(r0e, U2, mul2(r1e, U0));
            const u64 T3 = fma2(r0o, U3, mul2(r1o, U1));
            // A (packed)
            const u64 W0 = fma2(C0p, T0, mul2(S0p, T1));
            const u64 W1 = fma2(C0p, T1, mul2(S0p, T0));
            const u64 W2 = fma2(C0p, T2, mul2(S0p, T3));
            const u64 W3 = fma2(C0p, T3, mul2(S0p, T2));
            // B (scalar) + repack
            float w0,w1,w2,w3,w4,w5,w6,w7;
            upk(W0,w0,w1); upk(W1,w2,w3); upk(W2,w4,w5); upk(W3,w6,w7);
            U0 = pk(fmaf(C0,w0,S0*w1), fmaf(C0,w1,S0*w0));
            U1 = pk(fmaf(C0,w2,S0*w3), fmaf(C0,w3,S0*w2));
            U2 = pk(fmaf(C0,w4,S0*w5), fmaf(C0,w5,S0*w4));
            U3 = pk(fmaf(C0,w6,S0*w7), fmaf(C0,w7,S0*w6));
            g_sS[k][b][0] = U0; g_sS[k][b][1] = U1;
            g_sS[k][b][2] = U2; g_sS[k][b][3] = U3;
        }
    }
    __syncthreads();

    // ---- phase 3: readout split 5/5/4/4 across all warps ----
    if (active) {
        const int st = (wid < 2) ? wid * 5 : 10 + (wid - 2) * 4;
        const int en = st + ((wid < 2) ? 5 : 4);
        #pragma unroll
        for (int i = st; i < en; i++) {
            const u64 M0 = mul2(g_sL[i][b][0], g_sS[i][b][0]);
            const u64 M1 = mul2(g_sL[i][b][1], g_sS[i][b][1]);
            const u64 M2 = mul2(g_sL[i][b][2], g_sS[i][b][2]);   // w=1
            const u64 M3 = mul2(g_sL[i][b][3], g_sS[i][b][3]);   // w=1
            const u64 Ap = add2(M0, M1);
            const u64 An = add2(M2, M3);
            float pl, ph, nl, nh;
            upk(Ap, pl, ph); upk(An, nl, nh);
            out[b * NQ + i] = (pl + ph) - (nl + nh);
        }
    }
}

extern "C" void kernel_launch(void* const* d_in, const int* in_sizes, int n_in,
                              void* d_out, int out_size) {
    const float* in  = (const float*)d_in[0];
    float*       out = (float*)d_out;
    quantum_mps_kernel<<<1, 128>>>(in, out);
}